// round 15
// baseline (speedup 1.0000x reference)
#include <cuda_runtime.h>
#include <cuda_bf16.h>
#include <cstdint>
#include <cmath>

// Problem constants
constexpr int Nn  = 2048;   // tokens
constexpr int Dk  = 1024;   // model dim
constexpr int Hh  = 16;     // q heads
constexpr int KVh = 4;      // kv heads
constexpr int DHd = 64;     // head dim
constexpr int Ee  = 8;      // experts
constexpr int Ff  = 2048;   // ffn dim
constexpr int CHc = 64;     // ctrl hidden
constexpr float EPS = 1e-6f;
constexpr float DT  = 0.1f;
constexpr float BASE_SCALE = 10.0f;

// ---------------- device scratch (static, allowed) ----------------
__device__ float g_h1[Nn * Dk];
__device__ float g_q[Nn * Hh * DHd];
__device__ float g_k[Nn * KVh * DHd];
__device__ float g_v[Nn * KVh * DHd];
__device__ float g_o[Nn * Hh * DHd];
__device__ float g_oproj[Nn * Dk];
__device__ float g_ctrl[Nn * CHc];
__device__ float g_co[Nn * 3 * Dk];
__device__ float g_hidden2[Nn * Dk];
__device__ float g_x2[Nn * Dk];
__device__ float g_mid[Nn * Ff];
__device__ int   g_counts[Ee];
__device__ int   g_list[Ee * Nn];

// ---------------- tf32 helpers ----------------
__device__ __forceinline__ uint32_t cvt_tf32(float x) {
    uint32_t r;
    asm("cvt.rna.tf32.f32 %0, %1;" : "=r"(r) : "f"(x));
    return r;
}

__device__ __forceinline__ void mma_tf32(float c[4],
    uint32_t a0, uint32_t a1, uint32_t a2, uint32_t a3,
    uint32_t b0, uint32_t b1)
{
    asm volatile("mma.sync.aligned.m16n8k8.row.col.f32.tf32.tf32.f32 "
        "{%0,%1,%2,%3}, {%4,%5,%6,%7}, {%8,%9}, {%0,%1,%2,%3};"
        : "+f"(c[0]), "+f"(c[1]), "+f"(c[2]), "+f"(c[3])
        : "r"(a0), "r"(a1), "r"(a2), "r"(a3), "r"(b0), "r"(b1));
}

// fast exp via 2^f polynomial (rel err ~8e-6)
__device__ __forceinline__ float fexp(float x) {
    float t = x * 1.442695040888963f;
    t = fmaxf(t, -126.0f);
    int i = __float2int_rd(t);
    float f = t - (float)i;
    float p =         1.540353039e-4f;
    p = fmaf(p, f, 1.333355815e-3f);
    p = fmaf(p, f, 9.618129108e-3f);
    p = fmaf(p, f, 5.550410866e-2f);
    p = fmaf(p, f, 2.402265070e-1f);
    p = fmaf(p, f, 6.931471806e-1f);
    p = fmaf(p, f, 1.0f);
    return p * __int_as_float((i + 127) << 23);
}

__device__ __forceinline__ void cp_async16(uint32_t saddr, const void* gptr) {
    asm volatile("cp.async.ca.shared.global [%0], [%1], 16;" :: "r"(saddr), "l"(gptr));
}
__device__ __forceinline__ void cp_commit() {
    asm volatile("cp.async.commit_group;");
}
__device__ __forceinline__ void cp_wait0() {
    asm volatile("cp.async.wait_group 0;");
}

// ============================================================================
// Unified tf32 tensor-core GEMM: C[M,N] = act(A@B (+A2@B2) (+bias)) (+res)
// BM=128, BN=128 or 64, BK=16, 256 threads, double-buffered smem.
// ============================================================================
template<bool GATHER, bool DUAL, bool RES, int BN, int ACT>
__global__ __launch_bounds__(256, 1)
void mma_gemm_kernel(const float* __restrict__ A, const float* __restrict__ Bw,
                     const float* __restrict__ A2, const float* __restrict__ B2,
                     const float* __restrict__ bias, const float* __restrict__ res,
                     float* __restrict__ C, int N, int K, int lda, int ldc)
{
    constexpr int MT = (BN == 128) ? 4 : 2;
    __shared__ uint32_t As[2][16][136];
    __shared__ uint32_t Bs[2][16][BN + 8];
    __shared__ int toks[128];

    const float* B = Bw;
    int row0 = blockIdx.y * 128;
    if (GATHER) {
        int e = blockIdx.z;
        int cnt = g_counts[e];
        if (row0 >= cnt) return;
        B += (size_t)e * K * N;
        if (threadIdx.x < 128) {
            int idx = row0 + threadIdx.x;
            toks[threadIdx.x] = (idx < cnt) ? g_list[e * Nn + idx] : -1;
        }
        __syncthreads();
    }
    int col0 = blockIdx.x * BN;
    int tid  = threadIdx.x;
    int lane = tid & 31, warp = tid >> 5;
    int grp = lane >> 2, tig = lane & 3;
    int wm = (BN == 128) ? (warp >> 2) * 64 : (warp >> 1) * 32;
    int wn = (BN == 128) ? (warp & 3) * 32 : (warp & 1) * 32;

    int rowA = tid >> 1, colA = (tid & 1) << 3;
    int rB128 = tid >> 5, cB128 = (lane) << 2;
    int rB64  = tid >> 4, cB64  = (tid & 15) << 2;

    long aRow = GATHER ? (long)toks[rowA] : (long)(row0 + rowA);

    float c[MT][4][4];
    #pragma unroll
    for (int i = 0; i < MT; i++)
        #pragma unroll
        for (int j = 0; j < 4; j++)
            #pragma unroll
            for (int l = 0; l < 4; l++) c[i][j][l] = 0.f;

    const int TK = K / 16;
    const int T = (DUAL ? 2 : 1) * TK;
    float4 pa0, pa1, pb0, pb1;

    auto ldg = [&](int t) {
        int pass = DUAL ? (t >= TK) : 0;
        int k0 = (pass ? t - TK : t) << 4;
        const float* Ap = pass ? A2 : A;
        const float* Bp = pass ? B2 : B;
        if (!GATHER || aRow >= 0) {
            const float* ar = Ap + (size_t)aRow * lda + k0 + colA;
            pa0 = *(const float4*)ar;
            pa1 = *(const float4*)(ar + 4);
        } else {
            pa0 = make_float4(0, 0, 0, 0);
            pa1 = make_float4(0, 0, 0, 0);
        }
        if (BN == 128) {
            pb0 = *(const float4*)&Bp[(size_t)(k0 + rB128) * N + col0 + cB128];
            pb1 = *(const float4*)&Bp[(size_t)(k0 + rB128 + 8) * N + col0 + cB128];
        } else {
            pb0 = *(const float4*)&Bp[(size_t)(k0 + rB64) * N + col0 + cB64];
        }
    };
    auto sts = [&](int db) {
        As[db][colA + 0][rowA] = cvt_tf32(pa0.x);
        As[db][colA + 1][rowA] = cvt_tf32(pa0.y);
        As[db][colA + 2][rowA] = cvt_tf32(pa0.z);
        As[db][colA + 3][rowA] = cvt_tf32(pa0.w);
        As[db][colA + 4][rowA] = cvt_tf32(pa1.x);
        As[db][colA + 5][rowA] = cvt_tf32(pa1.y);
        As[db][colA + 6][rowA] = cvt_tf32(pa1.z);
        As[db][colA + 7][rowA] = cvt_tf32(pa1.w);
        if (BN == 128) {
            Bs[db][rB128][cB128 + 0] = cvt_tf32(pb0.x);
            Bs[db][rB128][cB128 + 1] = cvt_tf32(pb0.y);
            Bs[db][rB128][cB128 + 2] = cvt_tf32(pb0.z);
            Bs[db][rB128][cB128 + 3] = cvt_tf32(pb0.w);
            Bs[db][rB128 + 8][cB128 + 0] = cvt_tf32(pb1.x);
            Bs[db][rB128 + 8][cB128 + 1] = cvt_tf32(pb1.y);
            Bs[db][rB128 + 8][cB128 + 2] = cvt_tf32(pb1.z);
            Bs[db][rB128 + 8][cB128 + 3] = cvt_tf32(pb1.w);
        } else {
            Bs[db][rB64][cB64 + 0] = cvt_tf32(pb0.x);
            Bs[db][rB64][cB64 + 1] = cvt_tf32(pb0.y);
            Bs[db][rB64][cB64 + 2] = cvt_tf32(pb0.z);
            Bs[db][rB64][cB64 + 3] = cvt_tf32(pb0.w);
        }
    };
    auto compute = [&](int db) {
        #pragma unroll
        for (int ks = 0; ks < 16; ks += 8) {
            uint32_t af[MT][4], bf[4][2];
            #pragma unroll
            for (int mt = 0; mt < MT; ++mt) {
                int m = wm + mt * 16 + grp;
                af[mt][0] = As[db][ks + tig][m];
                af[mt][1] = As[db][ks + tig][m + 8];
                af[mt][2] = As[db][ks + tig + 4][m];
                af[mt][3] = As[db][ks + tig + 4][m + 8];
            }
            #pragma unroll
            for (int nt = 0; nt < 4; ++nt) {
                int n = wn + nt * 8 + grp;
                bf[nt][0] = Bs[db][ks + tig][n];
                bf[nt][1] = Bs[db][ks + tig + 4][n];
            }
            #pragma unroll
            for (int mt = 0; mt < MT; ++mt)
                #pragma unroll
                for (int nt = 0; nt < 4; ++nt)
                    mma_tf32(c[mt][nt], af[mt][0], af[mt][1], af[mt][2], af[mt][3],
                             bf[nt][0], bf[nt][1]);
        }
    };

    ldg(0);
    sts(0);
    if (T > 1) ldg(1);
    __syncthreads();
    for (int t = 0; t < T; ++t) {
        if (t + 1 < T) sts((t + 1) & 1);
        if (t + 2 < T) ldg(t + 2);
        compute(t & 1);
        __syncthreads();
    }

    #pragma unroll
    for (int mt = 0; mt < MT; ++mt) {
        #pragma unroll
        for (int h = 0; h < 2; ++h) {
            int rl = wm + mt * 16 + grp + h * 8;
            long orow;
            if (GATHER) {
                int tk = toks[rl];
                if (tk < 0) continue;
                orow = tk;
            } else {
                orow = row0 + rl;
            }
            #pragma unroll
            for (int nt = 0; nt < 4; ++nt) {
                int cg = col0 + wn + nt * 8 + tig * 2;
                float v0 = c[mt][nt][h * 2 + 0];
                float v1 = c[mt][nt][h * 2 + 1];
                if (bias) { v0 += bias[cg]; v1 += bias[cg + 1]; }
                if (ACT == 1) {
                    v0 = v0 / (1.f + expf(-v0));
                    v1 = v1 / (1.f + expf(-v1));
                }
                if (RES)  { v0 += res[orow * ldc + cg]; v1 += res[orow * ldc + cg + 1]; }
                *(float2*)&C[orow * ldc + cg] = make_float2(v0, v1);
            }
        }
    }
}

// ============================================================================
// Fused QKV tf32 GEMM: per-bx routing. 12 x-blocks: 8 Q, 2 K, 2 V. DUAL pass.
// V outputs (bx>=10) are rounded to tf32 grid (attention reads them raw).
// ============================================================================
__global__ __launch_bounds__(256, 1)
void qkv_mma_kernel(const float* __restrict__ h1, const float* __restrict__ mu,
                    const float* __restrict__ wq, const float* __restrict__ wmq,
                    const float* __restrict__ wk, const float* __restrict__ wmk,
                    const float* __restrict__ wv, const float* __restrict__ wmv,
                    float* __restrict__ qo, float* __restrict__ ko, float* __restrict__ vo)
{
    __shared__ uint32_t As[2][16][136];
    __shared__ uint32_t Bs[2][16][136];
    int bx = blockIdx.x;
    const float *B0, *B1; float* Cp; int Nout, colbase;
    if (bx < 8)       { B0 = wq; B1 = wmq; Cp = qo; Nout = 1024; colbase = bx * 128; }
    else if (bx < 10) { B0 = wk; B1 = wmk; Cp = ko; Nout = 256;  colbase = (bx - 8) * 128; }
    else              { B0 = wv; B1 = wmv; Cp = vo; Nout = 256;  colbase = (bx - 10) * 128; }
    bool roundV = (bx >= 10);
    int row0 = blockIdx.y * 128;
    int tid  = threadIdx.x;
    int lane = tid & 31, warp = tid >> 5;
    int grp = lane >> 2, tig = lane & 3;
    int wm = (warp >> 2) * 64;
    int wn = (warp & 3) * 32;
    int rowA = tid >> 1, colA = (tid & 1) << 3;
    int rB = tid >> 5, cB = lane << 2;

    float c[4][4][4];
    #pragma unroll
    for (int i = 0; i < 4; i++)
        #pragma unroll
        for (int j = 0; j < 4; j++)
            #pragma unroll
            for (int l = 0; l < 4; l++) c[i][j][l] = 0.f;

    const int TK = Dk / 16;        // 64
    const int T = 2 * TK;          // 128
    float4 pa0, pa1, pb0, pb1;
    auto ldg = [&](int t) {
        int pass = (t >= TK);
        int k0 = (pass ? t - TK : t) << 4;
        const float* Ap = pass ? mu : h1;
        const float* Bp = pass ? B1 : B0;
        const float* ar = Ap + (size_t)(row0 + rowA) * Dk + k0 + colA;
        pa0 = *(const float4*)ar;
        pa1 = *(const float4*)(ar + 4);
        pb0 = *(const float4*)&Bp[(size_t)(k0 + rB) * Nout + colbase + cB];
        pb1 = *(const float4*)&Bp[(size_t)(k0 + rB + 8) * Nout + colbase + cB];
    };
    auto sts = [&](int db) {
        As[db][colA + 0][rowA] = cvt_tf32(pa0.x);
        As[db][colA + 1][rowA] = cvt_tf32(pa0.y);
        As[db][colA + 2][rowA] = cvt_tf32(pa0.z);
        As[db][colA + 3][rowA] = cvt_tf32(pa0.w);
        As[db][colA + 4][rowA] = cvt_tf32(pa1.x);
        As[db][colA + 5][rowA] = cvt_tf32(pa1.y);
        As[db][colA + 6][rowA] = cvt_tf32(pa1.z);
        As[db][colA + 7][rowA] = cvt_tf32(pa1.w);
        Bs[db][rB][cB + 0] = cvt_tf32(pb0.x);
        Bs[db][rB][cB + 1] = cvt_tf32(pb0.y);
        Bs[db][rB][cB + 2] = cvt_tf32(pb0.z);
        Bs[db][rB][cB + 3] = cvt_tf32(pb0.w);
        Bs[db][rB + 8][cB + 0] = cvt_tf32(pb1.x);
        Bs[db][rB + 8][cB + 1] = cvt_tf32(pb1.y);
        Bs[db][rB + 8][cB + 2] = cvt_tf32(pb1.z);
        Bs[db][rB + 8][cB + 3] = cvt_tf32(pb1.w);
    };
    auto compute = [&](int db) {
        #pragma unroll
        for (int ks = 0; ks < 16; ks += 8) {
            uint32_t af[4][4], bf[4][2];
            #pragma unroll
            for (int mt = 0; mt < 4; ++mt) {
                int m = wm + mt * 16 + grp;
                af[mt][0] = As[db][ks + tig][m];
                af[mt][1] = As[db][ks + tig][m + 8];
                af[mt][2] = As[db][ks + tig + 4][m];
                af[mt][3] = As[db][ks + tig + 4][m + 8];
            }
            #pragma unroll
            for (int nt = 0; nt < 4; ++nt) {
                int n = wn + nt * 8 + grp;
                bf[nt][0] = Bs[db][ks + tig][n];
                bf[nt][1] = Bs[db][ks + tig + 4][n];
            }
            #pragma unroll
            for (int mt = 0; mt < 4; ++mt)
                #pragma unroll
                for (int nt = 0; nt < 4; ++nt)
                    mma_tf32(c[mt][nt], af[mt][0], af[mt][1], af[mt][2], af[mt][3],
                             bf[nt][0], bf[nt][1]);
        }
    };
    ldg(0);
    sts(0);
    ldg(1);
    __syncthreads();
    for (int t = 0; t < T; ++t) {
        if (t + 1 < T) sts((t + 1) & 1);
        if (t + 2 < T) ldg(t + 2);
        compute(t & 1);
        __syncthreads();
    }
    #pragma unroll
    for (int mt = 0; mt < 4; ++mt) {
        #pragma unroll
        for (int h = 0; h < 2; ++h) {
            int rl = wm + mt * 16 + grp + h * 8;
            long orow = row0 + rl;
            #pragma unroll
            for (int nt = 0; nt < 4; ++nt) {
                int cg = colbase + wn + nt * 8 + tig * 2;
                float v0 = c[mt][nt][h * 2 + 0];
                float v1 = c[mt][nt][h * 2 + 1];
                if (roundV) {
                    v0 = __uint_as_float(cvt_tf32(v0));
                    v1 = __uint_as_float(cvt_tf32(v1));
                }
                *(float2*)&Cp[orow * Nout + cg] = make_float2(v0, v1);
            }
        }
    }
}

// ============================================================================
// Tensor-core flash attention v4:
// 64 q-rows/CTA, 128 threads (4 warps). Inputs pre-rounded to tf32 (no cvt in
// loop). Separate K/V smem buffers (dynamic, 52.2KB): V loads overlap S
// compute; next-K loads overlap PV compute. 2 syncs/tile. Register softmax.
// ============================================================================
__global__ __launch_bounds__(128, 1)
void attn_mma_kernel(const float* __restrict__ q, const float* __restrict__ k,
                     const float* __restrict__ v, float* __restrict__ o)
{
    extern __shared__ float dynsm[];
    float*    Kf = dynsm;                       // [64][68]
    float*    Vf = dynsm + 64 * 68;             // [64][68]
    uint32_t* Ps = (uint32_t*)(dynsm + 2 * 64 * 68);   // [64][68]

    int h = blockIdx.y;
    int kvh = h >> 2;
    int q0 = blockIdx.x * 64;
    int tid = threadIdx.x;
    int lane = tid & 31, warp = tid >> 5;
    int grp = lane >> 2, tig = lane & 3;
    int wr0 = warp * 16;
    int ldr = tid >> 1, ldc = (tid & 1) * 32;

    uint32_t k_s = (uint32_t)__cvta_generic_to_shared(Kf);
    uint32_t v_s = (uint32_t)__cvta_generic_to_shared(Vf);

    // issue K(0)
    {
        const float* src = k + ((size_t)ldr * KVh + kvh) * DHd + ldc;
        uint32_t dst = k_s + (ldr * 68 + ldc) * 4;
        #pragma unroll
        for (int i = 0; i < 8; ++i) cp_async16(dst + i * 16, src + i * 4);
        cp_commit();
    }

    // Q fragments direct from gmem (pre-rounded tf32 bits, pre-scaled by 1/8)
    uint32_t qf[8][4];
    {
        const float* q0p = q + ((size_t)(q0 + wr0 + grp) * Hh + h) * DHd;
        const float* q1p = q + ((size_t)(q0 + wr0 + grp + 8) * Hh + h) * DHd;
        #pragma unroll
        for (int ks = 0; ks < 8; ++ks) {
            qf[ks][0] = __float_as_uint(q0p[ks * 8 + tig]);
            qf[ks][1] = __float_as_uint(q1p[ks * 8 + tig]);
            qf[ks][2] = __float_as_uint(q0p[ks * 8 + tig + 4]);
            qf[ks][3] = __float_as_uint(q1p[ks * 8 + tig + 4]);
        }
    }

    float m0 = -1e30f, m1 = -1e30f, l0 = 0.f, l1 = 0.f;
    float acc[8][4];
    #pragma unroll
    for (int dt = 0; dt < 8; ++dt)
        #pragma unroll
        for (int l = 0; l < 4; ++l) acc[dt][l] = 0.f;

    const int NT = Nn / 64;   // 32
    for (int kt = 0; kt < NT; ++kt) {
        cp_wait0();
        __syncthreads();      // K(kt) visible; V buffer free (prior PV done)

        // issue V(kt) — overlaps S compute
        {
            const float* src = v + ((size_t)(kt * 64 + ldr) * KVh + kvh) * DHd + ldc;
            uint32_t dst = v_s + (ldr * 68 + ldc) * 4;
            #pragma unroll
            for (int i = 0; i < 8; ++i) cp_async16(dst + i * 16, src + i * 4);
            cp_commit();
        }

        // ---- S = Q @ K^T (scores already scaled; no cvt needed) ----
        float cs[8][4];
        #pragma unroll
        for (int nt = 0; nt < 8; ++nt)
            #pragma unroll
            for (int l = 0; l < 4; ++l) cs[nt][l] = 0.f;
        #pragma unroll
        for (int ks = 0; ks < 8; ++ks) {
            #pragma unroll
            for (int nt = 0; nt < 8; ++nt) {
                uint32_t b0 = __float_as_uint(Kf[(nt * 8 + grp) * 68 + ks * 8 + tig]);
                uint32_t b1 = __float_as_uint(Kf[(nt * 8 + grp) * 68 + ks * 8 + tig + 4]);
                mma_tf32(cs[nt], qf[ks][0], qf[ks][1], qf[ks][2], qf[ks][3], b0, b1);
            }
        }

        // ---- register softmax ----
        float mx0 = -1e30f, mx1 = -1e30f;
        #pragma unroll
        for (int nt = 0; nt < 8; ++nt) {
            mx0 = fmaxf(mx0, fmaxf(cs[nt][0], cs[nt][1]));
            mx1 = fmaxf(mx1, fmaxf(cs[nt][2], cs[nt][3]));
        }
        mx0 = fmaxf(mx0, __shfl_xor_sync(0xffffffffu, mx0, 1));
        mx0 = fmaxf(mx0, __shfl_xor_sync(0xffffffffu, mx0, 2));
        mx1 = fmaxf(mx1, __shfl_xor_sync(0xffffffffu, mx1, 1));
        mx1 = fmaxf(mx1, __shfl_xor_sync(0xffffffffu, mx1, 2));
        float mnew0 = fmaxf(m0, mx0), mnew1 = fmaxf(m1, mx1);
        float corr0 = fexp(m0 - mnew0), corr1 = fexp(m1 - mnew1);
        float ls0 = 0.f, ls1 = 0.f;
        #pragma unroll
        for (int nt = 0; nt < 8; ++nt) {
            float p00 = fexp(cs[nt][0] - mnew0);
            float p01 = fexp(cs[nt][1] - mnew0);
            float p10 = fexp(cs[nt][2] - mnew1);
            float p11 = fexp(cs[nt][3] - mnew1);
            ls0 += p00 + p01;
            ls1 += p10 + p11;
            int cg = nt * 8 + tig * 2;
            Ps[(wr0 + grp) * 68 + cg]         = cvt_tf32(p00);
            Ps[(wr0 + grp) * 68 + cg + 1]     = cvt_tf32(p01);
            Ps[(wr0 + grp + 8) * 68 + cg]     = cvt_tf32(p10);
            Ps[(wr0 + grp + 8) * 68 + cg + 1] = cvt_tf32(p11);
        }
        ls0 += __shfl_xor_sync(0xffffffffu, ls0, 1);
        ls0 += __shfl_xor_sync(0xffffffffu, ls0, 2);
        ls1 += __shfl_xor_sync(0xffffffffu, ls1, 1);
        ls1 += __shfl_xor_sync(0xffffffffu, ls1, 2);
        l0 = l0 * corr0 + ls0;  m0 = mnew0;
        l1 = l1 * corr1 + ls1;  m1 = mnew1;
        #pragma unroll
        for (int dt = 0; dt < 8; ++dt) {
            acc[dt][0] *= corr0; acc[dt][1] *= corr0;
            acc[dt][2] *= corr1; acc[dt][3] *= corr1;
        }

        cp_wait0();
        __syncthreads();      // V(kt) visible; all warps past S (K buffer free)

        // issue K(kt+1) — overlaps PV compute
        if (kt + 1 < NT) {
            const float* src = k + ((size_t)((kt + 1) * 64 + ldr) * KVh + kvh) * DHd + ldc;
            uint32_t dst = k_s + (ldr * 68 + ldc) * 4;
            #pragma unroll
            for (int i = 0; i < 8; ++i) cp_async16(dst + i * 16, src + i * 4);
            cp_commit();
        }

        // ---- O += P @ V (P warp-private; no cvt on V) ----
        #pragma unroll
        for (int ks = 0; ks < 8; ++ks) {
            uint32_t a0 = Ps[(wr0 + grp) * 68 + ks * 8 + tig];
            uint32_t a1 = Ps[(wr0 + grp + 8) * 68 + ks * 8 + tig];
            uint32_t a2 = Ps[(wr0 + grp) * 68 + ks * 8 + tig + 4];
            uint32_t a3 = Ps[(wr0 + grp + 8) * 68 + ks * 8 + tig + 4];
            #pragma unroll
            for (int dt = 0; dt < 8; ++dt) {
                uint32_t b0 = __float_as_uint(Vf[(ks * 8 + tig) * 68 + dt * 8 + grp]);
                uint32_t b1 = __float_as_uint(Vf[(ks * 8 + tig + 4) * 68 + dt * 8 + grp]);
                mma_tf32(acc[dt], a0, a1, a2, a3, b0, b1);
            }
        }
    }

    // epilogue
    float r0inv = 1.f / l0, r1inv = 1.f / l1;
    int row0g = q0 + wr0 + grp;
    int row1g = row0g + 8;
    #pragma unroll
    for (int dt = 0; dt < 8; ++dt) {
        int cg = dt * 8 + tig * 2;
        *(float2*)&o[((size_t)row0g * Hh + h) * DHd + cg] =
            make_float2(acc[dt][0] * r0inv, acc[dt][1] * r0inv);
        *(float2*)&o[((size_t)row1g * Hh + h) * DHd + cg] =
            make_float2(acc[dt][2] * r1inv, acc[dt][3] * r1inv);
    }
}
constexpr int ATTN_DSMEM = 3 * 64 * 68 * 4;   // 52224 bytes

// ============================================================================
// Fused MoE gate+up (gathered tf32): Mid = silu(X@Wg) * (X@Wu)
// BM=128, BN=64, dual B tiles + dual accumulators.
// ============================================================================
__global__ __launch_bounds__(256, 1)
void moe_gateup_mma(const float* __restrict__ X, const float* __restrict__ Wg,
                    const float* __restrict__ Wu, float* __restrict__ Mid)
{
    __shared__ uint32_t As[2][16][136];
    __shared__ uint32_t Bg[2][16][72];
    __shared__ uint32_t Bu[2][16][72];
    __shared__ int toks[128];

    int e = blockIdx.z;
    int cnt = g_counts[e];
    int row0 = blockIdx.y * 128;
    if (row0 >= cnt) return;
    const float* Wge = Wg + (size_t)e * Dk * Ff;
    const float* Wue = Wu + (size_t)e * Dk * Ff;
    int col0 = blockIdx.x * 64;
    int tid = threadIdx.x;
    if (tid < 128) {
        int idx = row0 + tid;
        toks[tid] = (idx < cnt) ? g_list[e * Nn + idx] : -1;
    }
    __syncthreads();
    int lane = tid & 31, warp = tid >> 5;
    int grp = lane >> 2, tig = lane & 3;
    int wm = (warp >> 1) * 32;
    int wn = (warp & 1) * 32;
    int rowA = tid >> 1, colA = (tid & 1) << 3;
    int rB = tid >> 4, cB = (tid & 15) << 2;
    long aRow = (long)toks[rowA];

    float cg2[2][4][4], cu2[2][4][4];
    #pragma unroll
    for (int i = 0; i < 2; i++)
        #pragma unroll
        for (int j = 0; j < 4; j++)
            #pragma unroll
            for (int l = 0; l < 4; l++) { cg2[i][j][l] = 0.f; cu2[i][j][l] = 0.f; }

    const int T = Dk / 16;    // 64
    float4 pa0, pa1, pg, pu;
    auto ldg = [&](int t) {
        int k0 = t << 4;
        if (aRow >= 0) {
            const float* ar = X + (size_t)aRow * Dk + k0 + colA;
            pa0 = *(const float4*)ar;
            pa1 = *(const float4*)(ar + 4);
        } else {
            pa0 = make_float4(0, 0, 0, 0);
            pa1 = make_float4(0, 0, 0, 0);
        }
        pg = *(const float4*)&Wge[(size_t)(k0 + rB) * Ff + col0 + cB];
        pu = *(const float4*)&Wue[(size_t)(k0 + rB) * Ff + col0 + cB];
    };
    auto sts = [&](int db) {
        As[db][colA + 0][rowA] = cvt_tf32(pa0.x);
        As[db][colA + 1][rowA] = cvt_tf32(pa0.y);
        As[db][colA + 2][rowA] = cvt_tf32(pa0.z);
        As[db][colA + 3][rowA] = cvt_tf32(pa0.w);
        As[db][colA + 4][rowA] = cvt_tf32(pa1.x);
        As[db][colA + 5][rowA] = cvt_tf32(pa1.y);
        As[db][colA + 6][rowA] = cvt_tf32(pa1.z);
        As[db][colA + 7][rowA] = cvt_tf32(pa1.w);
        Bg[db][rB][cB + 0] = cvt_tf32(pg.x);
        Bg[db][rB][cB + 1] = cvt_tf32(pg.y);
        Bg[db][rB][cB + 2] = cvt_tf32(pg.z);
        Bg[db][rB][cB + 3] = cvt_tf32(pg.w);
        Bu[db][rB][cB + 0] = cvt_tf32(pu.x);
        Bu[db][rB][cB + 1] = cvt_tf32(pu.y);
        Bu[db][rB][cB + 2] = cvt_tf32(pu.z);
        Bu[db][rB][cB + 3] = cvt_tf32(pu.w);
    };
    auto compute = [&](int db) {
        #pragma unroll
        for (int ks = 0; ks < 16; ks += 8) {
            uint32_t af[2][4], bgf[4][2], buf[4][2];
            #pragma unroll
            for (int mt = 0; mt < 2; ++mt) {
                int m = wm + mt * 16 + grp;
                af[mt][0] = As[db][ks + tig][m];
                af[mt][1] = As[db][ks + tig][m + 8];
                af[mt][2] = As[db][ks + tig + 4][m];
                af[mt][3] = As[db][ks + tig + 4][m + 8];
            }
            #pragma unroll
            for (int nt = 0; nt < 4; ++nt) {
                int n = wn + nt * 8 + grp;
                bgf[nt][0] = Bg[db][ks + tig][n];
                bgf[nt][1] = Bg[db][ks + tig + 4][n];
                buf[nt][0] = Bu[db][ks + tig][n];
                buf[nt][1] = Bu[db][ks + tig + 4][n];
            }
            #pragma unroll
            for (int mt = 0; mt < 2; ++mt)
                #pragma unroll
                for (int nt = 0; nt < 4; ++nt) {
                    mma_tf32(cg2[mt][nt], af[mt][0], af[mt][1], af[mt][2], af[mt][3],
                             bgf[nt][0], bgf[nt][1]);
                    mma_tf32(cu2[mt][nt], af[mt][0], af[mt][1], af[mt][2], af[mt][3],
                             buf[nt][0], buf[nt][1]);
                }
        }
    };

    ldg(0);
    sts(0);
    ldg(1);
    __syncthreads();
    for (int t = 0; t < T; ++t) {
        if (t + 1 < T) sts((t + 1) & 1);
        if (t + 2 < T) ldg(t + 2);
        compute(t & 1);
        __syncthreads();
    }

    #pragma unroll
    for (int mt = 0; mt < 2; ++mt) {
        #pragma unroll
        for (int hh = 0; hh < 2; ++hh) {
            int rl = wm + mt * 16 + grp + hh * 8;
            int tk = toks[rl];
            if (tk < 0) continue;
            #pragma unroll
            for (int nt = 0; nt < 4; ++nt) {
                int cg = col0 + wn + nt * 8 + tig * 2;
                float g0 = cg2[mt][nt][hh * 2 + 0];
                float g1 = cg2[mt][nt][hh * 2 + 1];
                float u0 = cu2[mt][nt][hh * 2 + 0];
                float u1 = cu2[mt][nt][hh * 2 + 1];
                g0 = g0 / (1.f + expf(-g0));
                g1 = g1 / (1.f + expf(-g1));
                *(float2*)&Mid[(size_t)tk * Ff + cg] = make_float2(g0 * u0, g1 * u1);
            }
        }
    }
}

// ---------------- rmsnorm (float4 vectorized) ----------------
__global__ void rmsnorm_kernel(const float* __restrict__ x, const float* __restrict__ w,
                               float* __restrict__ y)
{
    int n = blockIdx.x;
    const float4* xr = (const float4*)(x + (size_t)n * Dk);
    const float4* wr = (const float4*)w;
    float4*       yr = (float4*)(y + (size_t)n * Dk);
    float s = 0.f;
    float4 v = xr[threadIdx.x];
    s = v.x * v.x + v.y * v.y + v.z * v.z + v.w * v.w;
    __shared__ float red[8];
    int lane = threadIdx.x & 31, wid = threadIdx.x >> 5;
    #pragma unroll
    for (int o = 16; o; o >>= 1) s += __shfl_xor_sync(0xffffffffu, s, o);
    if (lane == 0) red[wid] = s;
    __syncthreads();
    if (wid == 0) {
        float t = (lane < 8) ? red[lane] : 0.f;
        #pragma unroll
        for (int o = 4; o; o >>= 1) t += __shfl_xor_sync(0xffffffffu, t, o);
        if (lane == 0) red[0] = rsqrtf(t / Dk + EPS);
    }
    __syncthreads();
    float rms = red[0];
    float4 wv = wr[threadIdx.x];
    float4 out;
    out.x = v.x * rms * wv.x;
    out.y = v.y * rms * wv.y;
    out.z = v.z * rms * wv.z;
    out.w = v.w * rms * wv.w;
    yr[threadIdx.x] = out;
}

// ---------------- q/k rmsnorm + rope (stores tf32-rounded; q pre-scaled) ----
__global__ void qknorm_rope_kernel(float* __restrict__ q, float* __restrict__ k,
                                   const int* __restrict__ positions,
                                   const float* __restrict__ qw, const float* __restrict__ kw)
{
    int n = blockIdx.x;
    int hh = blockIdx.y;
    float* x; const float* w;
    bool isQ = (hh < Hh);
    if (isQ) { x = q + ((size_t)n * Hh + hh) * DHd; w = qw; }
    else     { x = k + ((size_t)n * KVh + (hh - Hh)) * DHd; w = kw; }
    int lane = threadIdx.x;
    float x1 = x[lane], x2 = x[lane + 32];
    float s = x1 * x1 + x2 * x2;
    #pragma unroll
    for (int o = 16; o; o >>= 1) s += __shfl_xor_sync(0xffffffffu, s, o);
    float rms = rsqrtf(s / 64.f + EPS);
    float v1 = x1 * rms * w[lane];
    float v2 = x2 * rms * w[lane + 32];
    float inv = (float)exp(-(2.0 * (double)lane / 64.0) * log(10000.0));
    float ang = (float)positions[n] * inv;
    float c = cosf(ang), sn = sinf(ang);
    float o1 = v1 * c - v2 * sn;
    float o2 = v2 * c + v1 * sn;
    if (isQ) { o1 *= 0.125f; o2 *= 0.125f; }   // fold attention scale into q
    x[lane]      = __uint_as_float(cvt_tf32(o1));
    x[lane + 32] = __uint_as_float(cvt_tf32(o2));
}

// ---------------- dynamics (elementwise, float4) ----------------
__global__ void dynamics_kernel(const float4* __restrict__ hidden_in,
                                const float4* __restrict__ velocity,
                                const float4* __restrict__ oproj,
                                const float4* __restrict__ mu,
                                const float* __restrict__ co,
                                float4* __restrict__ v_out,
                                float4* __restrict__ hidden2)
{
    int idx = blockIdx.x * blockDim.x + threadIdx.x;
    if (idx >= Nn * Dk / 4) return;
    int n = idx / (Dk / 4), c4 = idx - n * (Dk / 4);
    const float4* cr = (const float4*)(co + (size_t)n * 3 * Dk);
    float4 a_raw  = cr[c4];
    float4 b_raw  = cr[Dk / 4 + c4];
    float4 gt_raw = cr[2 * Dk / 4 + c4];
    float4 ov  = oproj[idx];
    float4 muv = mu[idx];
    float4 vel = velocity[idx];
    float4 hin = hidden_in[idx];
    float4 vn, h2;
    #pragma unroll
    for (int j = 0; j < 4; ++j) {
        float ar = (&a_raw.x)[j], br = (&b_raw.x)[j], gr = (&gt_raw.x)[j];
        float alpha = 1.f / (1.f + expf(-ar));
        float sp = (br > 20.f) ? br : log1pf(expf(br));
        float beta = fminf(sp, 2.f);
        float gate = 1.f / (1.f + expf(-gr));
        float o = (&ov.x)[j];
        float err = o - (&muv.x)[j];
        float vv = alpha * (&vel.x)[j] - beta * err;
        vv = fminf(fmaxf(vv, -10.f), 10.f);
        (&vn.x)[j] = vv;
        (&h2.x)[j] = (&hin.x)[j] + o + DT * gate * vv;
    }
    v_out[idx] = vn;
    hidden2[idx] = h2;
}

// ---------------- router ----------------
__global__ void reset_counts_kernel()
{
    if (threadIdx.x < Ee) g_counts[threadIdx.x] = 0;
}

__global__ void router_kernel(const float* __restrict__ mu, const float* __restrict__ W,
                              const int* __restrict__ token_ids)
{
    int gwarp = (blockIdx.x * blockDim.x + threadIdx.x) >> 5;
    int lane = threadIdx.x & 31;
    if (gwarp >= Nn) return;
    float acc[Ee] = {};
    const float* m = mu + (size_t)gwarp * Dk;
    for (int d = lane; d < Dk; d += 32) {
        float mv = m[d];
        #pragma unroll
        for (int e = 0; e < Ee; ++e) acc[e] += mv * W[d * Ee + e];
    }
    #pragma unroll
    for (int o = 16; o; o >>= 1)
        #pragma unroll
        for (int e = 0; e < Ee; ++e) acc[e] += __shfl_xor_sync(0xffffffffu, acc[e], o);
    if (lane == 0) {
        int base = token_ids[gwarp] % Ee;
        int best = 0; float bv = -1e30f;
        #pragma unroll
        for (int e = 0; e < Ee; ++e) {
            float vv = acc[e] + (e == base ? BASE_SCALE : 0.f);
            if (vv > bv) { bv = vv; best = e; }
        }
        int pos = atomicAdd(&g_counts[best], 1);
        g_list[best * Nn + pos] = gwarp;
    }
}

// ---------------- launch ----------------
static float* sym(const void* s)
{
    void* p = nullptr;
    cudaGetSymbolAddress(&p, s);
    return (float*)p;
}

extern "C" void kernel_launch(void* const* d_in, const int* in_sizes, int n_in,
                              void* d_out, int out_size)
{
    const float* hidden        = (const float*)d_in[0];
    const int*   positions     = (const int*)  d_in[1];
    const float* velocity      = (const float*)d_in[2];
    const int*   token_ids     = (const int*)  d_in[3];
    const float* mu_prev       = (const float*)d_in[4];
    const float* ln1_w         = (const float*)d_in[5];
    const float* ln2_w         = (const float*)d_in[6];
    const float* wq            = (const float*)d_in[7];
    const float* wk            = (const float*)d_in[8];
    const float* wv            = (const float*)d_in[9];
    const float* wo            = (const float*)d_in[10];
    const float* w_mu_q        = (const float*)d_in[11];
    const float* w_mu_k        = (const float*)d_in[12];
    const float* w_mu_v        = (const float*)d_in[13];
    const float* qnorm_w       = (const float*)d_in[14];
    const float* knorm_w       = (const float*)d_in[15];
    const float* dyn_mu        = (const float*)d_in[16];
    const float* dyn_mu_proj_w = (const float*)d_in[17];
    const float* ctrl_in_w     = (const float*)d_in[18];
    const float* ctrl_in_b     = (const float*)d_in[19];
    const float* ctrl_out_w    = (const float*)d_in[20];
    const float* ctrl_out_b    = (const float*)d_in[21];
    const float* mu_router_w   = (const float*)d_in[22];
    const float* w_gate        = (const float*)d_in[23];
    const float* w_up          = (const float*)d_in[24];
    const float* w_down        = (const float*)d_in[25];

    float* out_hidden = (float*)d_out;
    float* out_v      = out_hidden + (size_t)Nn * Dk;
    float* out_mu     = out_v + (size_t)Nn * Dk;

    float* h1   = sym(g_h1);
    float* qb   = sym(g_q);
    float* kb   = sym(g_k);
    float* vb   = sym(g_v);
    float* ob   = sym(g_o);
    float* op   = sym(g_oproj);
    float* ctrl = sym(g_ctrl);
    float* co   = sym(g_co);
    float* h2   = sym(g_hidden2);
    float* x2   = sym(g_x2);
    float* mid  = sym(g_mid);

    cudaFuncSetAttribute(attn_mma_kernel,
                         cudaFuncAttributeMaxDynamicSharedMemorySize, ATTN_DSMEM);

    // 1) rmsnorm1
    rmsnorm_kernel<<<Nn, 256>>>(hidden, ln1_w, h1);

    // 2) fused QKV = h1@W + mu_prev@W_mu  (tf32 mma; V rounded to tf32 grid)
    qkv_mma_kernel<<<dim3(12, Nn / 128), 256>>>(h1, mu_prev, wq, w_mu_q, wk, w_mu_k,
                                                wv, w_mu_v, qb, kb, vb);

    // 3) q/k norm + rope (in place; stores tf32-rounded, q pre-scaled by 1/8)
    qknorm_rope_kernel<<<dim3(Nn, Hh + KVh), 32>>>(qb, kb, positions, qnorm_w, knorm_w);

    // 4) attention (tf32 mma v4: no in-loop cvt, overlapped cp.async, 2 syncs/tile)
    attn_mma_kernel<<<dim3(Nn / 64, Hh), 128, ATTN_DSMEM>>>(qb, kb, vb, ob);

    // 5) o-proj (tf32)
    mma_gemm_kernel<false, false, false, 128, 0><<<dim3(Dk / 128, Nn / 128), 256>>>(
        ob, wo, nullptr, nullptr, nullptr, nullptr, op, Dk, Hh * DHd, Hh * DHd, Dk);

    // 6) mu_cur = dyn_mu + oproj @ dyn_mu_proj_w (tf32, direct to output)
    mma_gemm_kernel<false, false, false, 128, 0><<<dim3(Dk / 128, Nn / 128), 256>>>(
        op, dyn_mu_proj_w, nullptr, nullptr, dyn_mu, nullptr, out_mu, Dk, Dk, Dk, Dk);

    // 7) ctrl = silu([o, velocity] @ ctrl_in_w + b)  (tf32 BN=64, dual, silu)
    mma_gemm_kernel<false, true, false, 64, 1><<<dim3(1, Nn / 128), 256>>>(
        op, ctrl_in_w, velocity, ctrl_in_w + (size_t)Dk * CHc, ctrl_in_b, nullptr,
        ctrl, CHc, Dk, Dk, CHc);

    // 8) co = ctrl @ ctrl_out_w + b  (tf32, K=64)
    mma_gemm_kernel<false, false, false, 128, 0><<<dim3(3 * Dk / 128, Nn / 128), 256>>>(
        ctrl, ctrl_out_w, nullptr, nullptr, ctrl_out_b, nullptr, co, 3 * Dk, CHc, CHc, 3 * Dk);

    // 9) dynamics: v_next (output), hidden2
    dynamics_kernel<<<(Nn * Dk / 4 + 255) / 256, 256>>>((const float4*)hidden, (const float4*)velocity,
                                                        (const float4*)op, (const float4*)out_mu, co,
                                                        (float4*)out_v, (float4*)h2);

    // 10) rmsnorm2
    rmsnorm_kernel<<<Nn, 256>>>(h2, ln2_w, x2);

    // 11) router
    reset_counts_kernel<<<1, 32>>>();
    router_kernel<<<(Nn * 32 + 255) / 256, 256>>>(out_mu, mu_router_w, token_ids);

    // 12) MoE fused gate+up -> Mid = silu(g)*u  (tf32, gathered)
    moe_gateup_mma<<<dim3(Ff / 64, Nn / 128, Ee), 256>>>(x2, w_gate, w_up, mid);

    // 13) MoE down + residual -> final hidden (tf32, gathered)
    mma_gemm_kernel<true, false, true, 128, 0><<<dim3(Dk / 128, Nn / 128, Ee), 256>>>(
        mid, w_down, nullptr, nullptr, nullptr, h2, out_hidden, Dk, Ff, Ff, Dk);
}

// round 16
// speedup vs baseline: 1.5553x; 1.5553x over previous
#include <cuda_runtime.h>
#include <cuda_bf16.h>
#include <cstdint>
#include <cmath>

// Problem constants
constexpr int Nn  = 2048;   // tokens
constexpr int Dk  = 1024;   // model dim
constexpr int Hh  = 16;     // q heads
constexpr int KVh = 4;      // kv heads
constexpr int DHd = 64;     // head dim
constexpr int Ee  = 8;      // experts
constexpr int Ff  = 2048;   // ffn dim
constexpr int CHc = 64;     // ctrl hidden
constexpr float EPS = 1e-6f;
constexpr float DT  = 0.1f;
constexpr float BASE_SCALE = 10.0f;

// ---------------- device scratch (static, allowed) ----------------
__device__ float g_h1[Nn * Dk];
__device__ float g_q[Nn * Hh * DHd];
__device__ float g_k[Nn * KVh * DHd];
__device__ float g_v[Nn * KVh * DHd];
__device__ float g_o[Nn * Hh * DHd];
__device__ float g_oproj[Nn * Dk];
__device__ float g_ctrl[Nn * CHc];
__device__ float g_co[Nn * 3 * Dk];
__device__ float g_hidden2[Nn * Dk];
__device__ float g_x2[Nn * Dk];
__device__ float g_midg[Nn * Ff];
__device__ float g_midu[Nn * Ff];
__device__ float g_mid[Nn * Ff];
__device__ int   g_counts[Ee];
__device__ int   g_list[Ee * Nn];

// ---------------- tf32 helpers ----------------
__device__ __forceinline__ uint32_t cvt_tf32(float x) {
    uint32_t r;
    asm("cvt.rna.tf32.f32 %0, %1;" : "=r"(r) : "f"(x));
    return r;
}

__device__ __forceinline__ void mma_tf32(float c[4],
    uint32_t a0, uint32_t a1, uint32_t a2, uint32_t a3,
    uint32_t b0, uint32_t b1)
{
    asm volatile("mma.sync.aligned.m16n8k8.row.col.f32.tf32.tf32.f32 "
        "{%0,%1,%2,%3}, {%4,%5,%6,%7}, {%8,%9}, {%0,%1,%2,%3};"
        : "+f"(c[0]), "+f"(c[1]), "+f"(c[2]), "+f"(c[3])
        : "r"(a0), "r"(a1), "r"(a2), "r"(a3), "r"(b0), "r"(b1));
}

// fast exp via 2^f polynomial (rel err ~8e-6)
__device__ __forceinline__ float fexp(float x) {
    float t = x * 1.442695040888963f;
    t = fmaxf(t, -126.0f);
    int i = __float2int_rd(t);
    float f = t - (float)i;
    float p =         1.540353039e-4f;
    p = fmaf(p, f, 1.333355815e-3f);
    p = fmaf(p, f, 9.618129108e-3f);
    p = fmaf(p, f, 5.550410866e-2f);
    p = fmaf(p, f, 2.402265070e-1f);
    p = fmaf(p, f, 6.931471806e-1f);
    p = fmaf(p, f, 1.0f);
    return p * __int_as_float((i + 127) << 23);
}

__device__ __forceinline__ void cp_async16(uint32_t saddr, const void* gptr) {
    asm volatile("cp.async.ca.shared.global [%0], [%1], 16;" :: "r"(saddr), "l"(gptr));
}
__device__ __forceinline__ void cp_commit() {
    asm volatile("cp.async.commit_group;");
}
__device__ __forceinline__ void cp_wait0() {
    asm volatile("cp.async.wait_group 0;");
}

// ============================================================================
// Unified tf32 tensor-core GEMM: C[M,N] = act(A@B (+A2@B2) (+bias)) (+res)
// BM=128, BN=128 or 64, BK=16, 256 threads, double-buffered smem.
// ============================================================================
template<bool GATHER, bool DUAL, bool RES, int BN, int ACT>
__global__ __launch_bounds__(256, 1)
void mma_gemm_kernel(const float* __restrict__ A, const float* __restrict__ Bw,
                     const float* __restrict__ A2, const float* __restrict__ B2,
                     const float* __restrict__ bias, const float* __restrict__ res,
                     float* __restrict__ C, int N, int K, int lda, int ldc)
{
    constexpr int MT = (BN == 128) ? 4 : 2;
    __shared__ uint32_t As[2][16][136];
    __shared__ uint32_t Bs[2][16][BN + 8];
    __shared__ int toks[128];

    const float* B = Bw;
    int row0 = blockIdx.y * 128;
    if (GATHER) {
        int e = blockIdx.z;
        int cnt = g_counts[e];
        if (row0 >= cnt) return;
        B += (size_t)e * K * N;
        if (threadIdx.x < 128) {
            int idx = row0 + threadIdx.x;
            toks[threadIdx.x] = (idx < cnt) ? g_list[e * Nn + idx] : -1;
        }
        __syncthreads();
    }
    int col0 = blockIdx.x * BN;
    int tid  = threadIdx.x;
    int lane = tid & 31, warp = tid >> 5;
    int grp = lane >> 2, tig = lane & 3;
    int wm = (BN == 128) ? (warp >> 2) * 64 : (warp >> 1) * 32;
    int wn = (BN == 128) ? (warp & 3) * 32 : (warp & 1) * 32;

    int rowA = tid >> 1, colA = (tid & 1) << 3;
    int rB128 = tid >> 5, cB128 = (lane) << 2;
    int rB64  = tid >> 4, cB64  = (tid & 15) << 2;

    long aRow = GATHER ? (long)toks[rowA] : (long)(row0 + rowA);

    float c[MT][4][4];
    #pragma unroll
    for (int i = 0; i < MT; i++)
        #pragma unroll
        for (int j = 0; j < 4; j++)
            #pragma unroll
            for (int l = 0; l < 4; l++) c[i][j][l] = 0.f;

    const int TK = K / 16;
    const int T = (DUAL ? 2 : 1) * TK;
    float4 pa0, pa1, pb0, pb1;

    auto ldg = [&](int t) {
        int pass = DUAL ? (t >= TK) : 0;
        int k0 = (pass ? t - TK : t) << 4;
        const float* Ap = pass ? A2 : A;
        const float* Bp = pass ? B2 : B;
        if (!GATHER || aRow >= 0) {
            const float* ar = Ap + (size_t)aRow * lda + k0 + colA;
            pa0 = *(const float4*)ar;
            pa1 = *(const float4*)(ar + 4);
        } else {
            pa0 = make_float4(0, 0, 0, 0);
            pa1 = make_float4(0, 0, 0, 0);
        }
        if (BN == 128) {
            pb0 = *(const float4*)&Bp[(size_t)(k0 + rB128) * N + col0 + cB128];
            pb1 = *(const float4*)&Bp[(size_t)(k0 + rB128 + 8) * N + col0 + cB128];
        } else {
            pb0 = *(const float4*)&Bp[(size_t)(k0 + rB64) * N + col0 + cB64];
        }
    };
    auto sts = [&](int db) {
        As[db][colA + 0][rowA] = cvt_tf32(pa0.x);
        As[db][colA + 1][rowA] = cvt_tf32(pa0.y);
        As[db][colA + 2][rowA] = cvt_tf32(pa0.z);
        As[db][colA + 3][rowA] = cvt_tf32(pa0.w);
        As[db][colA + 4][rowA] = cvt_tf32(pa1.x);
        As[db][colA + 5][rowA] = cvt_tf32(pa1.y);
        As[db][colA + 6][rowA] = cvt_tf32(pa1.z);
        As[db][colA + 7][rowA] = cvt_tf32(pa1.w);
        if (BN == 128) {
            Bs[db][rB128][cB128 + 0] = cvt_tf32(pb0.x);
            Bs[db][rB128][cB128 + 1] = cvt_tf32(pb0.y);
            Bs[db][rB128][cB128 + 2] = cvt_tf32(pb0.z);
            Bs[db][rB128][cB128 + 3] = cvt_tf32(pb0.w);
            Bs[db][rB128 + 8][cB128 + 0] = cvt_tf32(pb1.x);
            Bs[db][rB128 + 8][cB128 + 1] = cvt_tf32(pb1.y);
            Bs[db][rB128 + 8][cB128 + 2] = cvt_tf32(pb1.z);
            Bs[db][rB128 + 8][cB128 + 3] = cvt_tf32(pb1.w);
        } else {
            Bs[db][rB64][cB64 + 0] = cvt_tf32(pb0.x);
            Bs[db][rB64][cB64 + 1] = cvt_tf32(pb0.y);
            Bs[db][rB64][cB64 + 2] = cvt_tf32(pb0.z);
            Bs[db][rB64][cB64 + 3] = cvt_tf32(pb0.w);
        }
    };
    auto compute = [&](int db) {
        #pragma unroll
        for (int ks = 0; ks < 16; ks += 8) {
            uint32_t af[MT][4], bf[4][2];
            #pragma unroll
            for (int mt = 0; mt < MT; ++mt) {
                int m = wm + mt * 16 + grp;
                af[mt][0] = As[db][ks + tig][m];
                af[mt][1] = As[db][ks + tig][m + 8];
                af[mt][2] = As[db][ks + tig + 4][m];
                af[mt][3] = As[db][ks + tig + 4][m + 8];
            }
            #pragma unroll
            for (int nt = 0; nt < 4; ++nt) {
                int n = wn + nt * 8 + grp;
                bf[nt][0] = Bs[db][ks + tig][n];
                bf[nt][1] = Bs[db][ks + tig + 4][n];
            }
            #pragma unroll
            for (int mt = 0; mt < MT; ++mt)
                #pragma unroll
                for (int nt = 0; nt < 4; ++nt)
                    mma_tf32(c[mt][nt], af[mt][0], af[mt][1], af[mt][2], af[mt][3],
                             bf[nt][0], bf[nt][1]);
        }
    };

    ldg(0);
    sts(0);
    if (T > 1) ldg(1);
    __syncthreads();
    for (int t = 0; t < T; ++t) {
        if (t + 1 < T) sts((t + 1) & 1);
        if (t + 2 < T) ldg(t + 2);
        compute(t & 1);
        __syncthreads();
    }

    #pragma unroll
    for (int mt = 0; mt < MT; ++mt) {
        #pragma unroll
        for (int h = 0; h < 2; ++h) {
            int rl = wm + mt * 16 + grp + h * 8;
            long orow;
            if (GATHER) {
                int tk = toks[rl];
                if (tk < 0) continue;
                orow = tk;
            } else {
                orow = row0 + rl;
            }
            #pragma unroll
            for (int nt = 0; nt < 4; ++nt) {
                int cg = col0 + wn + nt * 8 + tig * 2;
                float v0 = c[mt][nt][h * 2 + 0];
                float v1 = c[mt][nt][h * 2 + 1];
                if (bias) { v0 += bias[cg]; v1 += bias[cg + 1]; }
                if (ACT == 1) {
                    v0 = v0 / (1.f + expf(-v0));
                    v1 = v1 / (1.f + expf(-v1));
                }
                if (RES)  { v0 += res[orow * ldc + cg]; v1 += res[orow * ldc + cg + 1]; }
                *(float2*)&C[orow * ldc + cg] = make_float2(v0, v1);
            }
        }
    }
}

// ============================================================================
// Fused QKV tf32 GEMM: per-bx routing. 12 x-blocks: 8 Q, 2 K, 2 V. DUAL pass.
// V outputs (bx>=10) rounded to tf32 grid (attention reads them raw).
// ============================================================================
__global__ __launch_bounds__(256, 1)
void qkv_mma_kernel(const float* __restrict__ h1, const float* __restrict__ mu,
                    const float* __restrict__ wq, const float* __restrict__ wmq,
                    const float* __restrict__ wk, const float* __restrict__ wmk,
                    const float* __restrict__ wv, const float* __restrict__ wmv,
                    float* __restrict__ qo, float* __restrict__ ko, float* __restrict__ vo)
{
    __shared__ uint32_t As[2][16][136];
    __shared__ uint32_t Bs[2][16][136];
    int bx = blockIdx.x;
    const float *B0, *B1; float* Cp; int Nout, colbase;
    if (bx < 8)       { B0 = wq; B1 = wmq; Cp = qo; Nout = 1024; colbase = bx * 128; }
    else if (bx < 10) { B0 = wk; B1 = wmk; Cp = ko; Nout = 256;  colbase = (bx - 8) * 128; }
    else              { B0 = wv; B1 = wmv; Cp = vo; Nout = 256;  colbase = (bx - 10) * 128; }
    bool roundV = (bx >= 10);
    int row0 = blockIdx.y * 128;
    int tid  = threadIdx.x;
    int lane = tid & 31, warp = tid >> 5;
    int grp = lane >> 2, tig = lane & 3;
    int wm = (warp >> 2) * 64;
    int wn = (warp & 3) * 32;
    int rowA = tid >> 1, colA = (tid & 1) << 3;
    int rB = tid >> 5, cB = lane << 2;

    float c[4][4][4];
    #pragma unroll
    for (int i = 0; i < 4; i++)
        #pragma unroll
        for (int j = 0; j < 4; j++)
            #pragma unroll
            for (int l = 0; l < 4; l++) c[i][j][l] = 0.f;

    const int TK = Dk / 16;        // 64
    const int T = 2 * TK;          // 128
    float4 pa0, pa1, pb0, pb1;
    auto ldg = [&](int t) {
        int pass = (t >= TK);
        int k0 = (pass ? t - TK : t) << 4;
        const float* Ap = pass ? mu : h1;
        const float* Bp = pass ? B1 : B0;
        const float* ar = Ap + (size_t)(row0 + rowA) * Dk + k0 + colA;
        pa0 = *(const float4*)ar;
        pa1 = *(const float4*)(ar + 4);
        pb0 = *(const float4*)&Bp[(size_t)(k0 + rB) * Nout + colbase + cB];
        pb1 = *(const float4*)&Bp[(size_t)(k0 + rB + 8) * Nout + colbase + cB];
    };
    auto sts = [&](int db) {
        As[db][colA + 0][rowA] = cvt_tf32(pa0.x);
        As[db][colA + 1][rowA] = cvt_tf32(pa0.y);
        As[db][colA + 2][rowA] = cvt_tf32(pa0.z);
        As[db][colA + 3][rowA] = cvt_tf32(pa0.w);
        As[db][colA + 4][rowA] = cvt_tf32(pa1.x);
        As[db][colA + 5][rowA] = cvt_tf32(pa1.y);
        As[db][colA + 6][rowA] = cvt_tf32(pa1.z);
        As[db][colA + 7][rowA] = cvt_tf32(pa1.w);
        Bs[db][rB][cB + 0] = cvt_tf32(pb0.x);
        Bs[db][rB][cB + 1] = cvt_tf32(pb0.y);
        Bs[db][rB][cB + 2] = cvt_tf32(pb0.z);
        Bs[db][rB][cB + 3] = cvt_tf32(pb0.w);
        Bs[db][rB + 8][cB + 0] = cvt_tf32(pb1.x);
        Bs[db][rB + 8][cB + 1] = cvt_tf32(pb1.y);
        Bs[db][rB + 8][cB + 2] = cvt_tf32(pb1.z);
        Bs[db][rB + 8][cB + 3] = cvt_tf32(pb1.w);
    };
    auto compute = [&](int db) {
        #pragma unroll
        for (int ks = 0; ks < 16; ks += 8) {
            uint32_t af[4][4], bf[4][2];
            #pragma unroll
            for (int mt = 0; mt < 4; ++mt) {
                int m = wm + mt * 16 + grp;
                af[mt][0] = As[db][ks + tig][m];
                af[mt][1] = As[db][ks + tig][m + 8];
                af[mt][2] = As[db][ks + tig + 4][m];
                af[mt][3] = As[db][ks + tig + 4][m + 8];
            }
            #pragma unroll
            for (int nt = 0; nt < 4; ++nt) {
                int n = wn + nt * 8 + grp;
                bf[nt][0] = Bs[db][ks + tig][n];
                bf[nt][1] = Bs[db][ks + tig + 4][n];
            }
            #pragma unroll
            for (int mt = 0; mt < 4; ++mt)
                #pragma unroll
                for (int nt = 0; nt < 4; ++nt)
                    mma_tf32(c[mt][nt], af[mt][0], af[mt][1], af[mt][2], af[mt][3],
                             bf[nt][0], bf[nt][1]);
        }
    };
    ldg(0);
    sts(0);
    ldg(1);
    __syncthreads();
    for (int t = 0; t < T; ++t) {
        if (t + 1 < T) sts((t + 1) & 1);
        if (t + 2 < T) ldg(t + 2);
        compute(t & 1);
        __syncthreads();
    }
    #pragma unroll
    for (int mt = 0; mt < 4; ++mt) {
        #pragma unroll
        for (int h = 0; h < 2; ++h) {
            int rl = wm + mt * 16 + grp + h * 8;
            long orow = row0 + rl;
            #pragma unroll
            for (int nt = 0; nt < 4; ++nt) {
                int cg = colbase + wn + nt * 8 + tig * 2;
                float v0 = c[mt][nt][h * 2 + 0];
                float v1 = c[mt][nt][h * 2 + 1];
                if (roundV) {
                    v0 = __uint_as_float(cvt_tf32(v0));
                    v1 = __uint_as_float(cvt_tf32(v1));
                }
                *(float2*)&Cp[orow * Nout + cg] = make_float2(v0, v1);
            }
        }
    }
}

// ============================================================================
// Tensor-core flash attention (v3 structure + pre-rounded inputs, no in-loop cvt):
// 64 q-rows/CTA, 128 threads (4 warps), warp owns 16 rows x ALL 64 keys.
// Softmax in registers. Q frags in registers (bits). Shared K/V smem buffer.
// ============================================================================
__global__ __launch_bounds__(128, 1)
void attn_mma_kernel(const float* __restrict__ q, const float* __restrict__ k,
                     const float* __restrict__ v, float* __restrict__ o)
{
    __shared__ float    KVf[64][68];   // K then V tile (tf32-valued fp32) 17.4 KB
    __shared__ uint32_t Ps[64][68];    // Q staging then P (tf32 bits) 17.4 KB

    int h = blockIdx.y;
    int kvh = h >> 2;
    int q0 = blockIdx.x * 64;
    int tid = threadIdx.x;
    int lane = tid & 31, warp = tid >> 5;
    int grp = lane >> 2, tig = lane & 3;
    int wr0 = warp * 16;
    int ldr = tid >> 1, ldc = (tid & 1) * 32;

    uint32_t kv_s = (uint32_t)__cvta_generic_to_shared(&KVf[0][0]);

    // issue cp.async for K tile 0 early
    {
        const float* src = k + ((size_t)ldr * KVh + kvh) * DHd + ldc;
        uint32_t dst = kv_s + (ldr * 68 + ldc) * 4;
        #pragma unroll
        for (int i = 0; i < 8; ++i) cp_async16(dst + i * 16, src + i * 4);
        cp_commit();
    }

    // stage Q bits into Ps (already tf32-rounded + pre-scaled by producer)
    {
        const float* src = q + ((size_t)(q0 + ldr) * Hh + h) * DHd + ldc;
        #pragma unroll
        for (int i = 0; i < 8; ++i) {
            float4 x = *(const float4*)(src + i * 4);
            Ps[ldr][ldc + i * 4 + 0] = __float_as_uint(x.x);
            Ps[ldr][ldc + i * 4 + 1] = __float_as_uint(x.y);
            Ps[ldr][ldc + i * 4 + 2] = __float_as_uint(x.z);
            Ps[ldr][ldc + i * 4 + 3] = __float_as_uint(x.w);
        }
    }
    __syncthreads();

    // Q fragments -> registers (32 regs)
    uint32_t qf[8][4];
    #pragma unroll
    for (int ks = 0; ks < 8; ++ks) {
        qf[ks][0] = Ps[wr0 + grp][ks * 8 + tig];
        qf[ks][1] = Ps[wr0 + grp + 8][ks * 8 + tig];
        qf[ks][2] = Ps[wr0 + grp][ks * 8 + tig + 4];
        qf[ks][3] = Ps[wr0 + grp + 8][ks * 8 + tig + 4];
    }

    float m0 = -1e30f, m1 = -1e30f, l0 = 0.f, l1 = 0.f;
    float acc[8][4];
    #pragma unroll
    for (int dt = 0; dt < 8; ++dt)
        #pragma unroll
        for (int l = 0; l < 4; ++l) acc[dt][l] = 0.f;

    const int NT = Nn / 64;   // 32
    for (int kt = 0; kt < NT; ++kt) {
        cp_wait0();
        __syncthreads();      // K tile ready

        // ---- S = Q @ K^T (no cvt; scale folded into q) ----
        float cs[8][4];
        #pragma unroll
        for (int nt = 0; nt < 8; ++nt)
            #pragma unroll
            for (int l = 0; l < 4; ++l) cs[nt][l] = 0.f;
        #pragma unroll
        for (int ks = 0; ks < 8; ++ks) {
            #pragma unroll
            for (int nt = 0; nt < 8; ++nt) {
                uint32_t b0 = __float_as_uint(KVf[nt * 8 + grp][ks * 8 + tig]);
                uint32_t b1 = __float_as_uint(KVf[nt * 8 + grp][ks * 8 + tig + 4]);
                mma_tf32(cs[nt], qf[ks][0], qf[ks][1], qf[ks][2], qf[ks][3], b0, b1);
            }
        }

        // ---- register softmax (rows wr0+grp and wr0+grp+8) ----
        float mx0 = -1e30f, mx1 = -1e30f;
        #pragma unroll
        for (int nt = 0; nt < 8; ++nt) {
            mx0 = fmaxf(mx0, fmaxf(cs[nt][0], cs[nt][1]));
            mx1 = fmaxf(mx1, fmaxf(cs[nt][2], cs[nt][3]));
        }
        mx0 = fmaxf(mx0, __shfl_xor_sync(0xffffffffu, mx0, 1));
        mx0 = fmaxf(mx0, __shfl_xor_sync(0xffffffffu, mx0, 2));
        mx1 = fmaxf(mx1, __shfl_xor_sync(0xffffffffu, mx1, 1));
        mx1 = fmaxf(mx1, __shfl_xor_sync(0xffffffffu, mx1, 2));
        float mnew0 = fmaxf(m0, mx0), mnew1 = fmaxf(m1, mx1);
        float corr0 = fexp(m0 - mnew0), corr1 = fexp(m1 - mnew1);
        float ls0 = 0.f, ls1 = 0.f;
        #pragma unroll
        for (int nt = 0; nt < 8; ++nt) {
            float p00 = fexp(cs[nt][0] - mnew0);
            float p01 = fexp(cs[nt][1] - mnew0);
            float p10 = fexp(cs[nt][2] - mnew1);
            float p11 = fexp(cs[nt][3] - mnew1);
            ls0 += p00 + p01;
            ls1 += p10 + p11;
            int cg = nt * 8 + tig * 2;
            Ps[wr0 + grp][cg]         = cvt_tf32(p00);
            Ps[wr0 + grp][cg + 1]     = cvt_tf32(p01);
            Ps[wr0 + grp + 8][cg]     = cvt_tf32(p10);
            Ps[wr0 + grp + 8][cg + 1] = cvt_tf32(p11);
        }
        ls0 += __shfl_xor_sync(0xffffffffu, ls0, 1);
        ls0 += __shfl_xor_sync(0xffffffffu, ls0, 2);
        ls1 += __shfl_xor_sync(0xffffffffu, ls1, 1);
        ls1 += __shfl_xor_sync(0xffffffffu, ls1, 2);
        l0 = l0 * corr0 + ls0;  m0 = mnew0;
        l1 = l1 * corr1 + ls1;  m1 = mnew1;
        #pragma unroll
        for (int dt = 0; dt < 8; ++dt) {
            acc[dt][0] *= corr0; acc[dt][1] *= corr0;
            acc[dt][2] *= corr1; acc[dt][3] *= corr1;
        }
        __syncthreads();      // all K reads done

        // ---- load V into KVf (overwrites K) ----
        {
            const float* src = v + ((size_t)(kt * 64 + ldr) * KVh + kvh) * DHd + ldc;
            uint32_t dst = kv_s + (ldr * 68 + ldc) * 4;
            #pragma unroll
            for (int i = 0; i < 8; ++i) cp_async16(dst + i * 16, src + i * 4);
            cp_commit();
        }
        cp_wait0();
        __syncthreads();      // V ready

        // ---- O += P @ V (no cvt on V) ----
        #pragma unroll
        for (int ks = 0; ks < 8; ++ks) {
            uint32_t a0 = Ps[wr0 + grp][ks * 8 + tig];
            uint32_t a1 = Ps[wr0 + grp + 8][ks * 8 + tig];
            uint32_t a2 = Ps[wr0 + grp][ks * 8 + tig + 4];
            uint32_t a3 = Ps[wr0 + grp + 8][ks * 8 + tig + 4];
            #pragma unroll
            for (int dt = 0; dt < 8; ++dt) {
                uint32_t b0 = __float_as_uint(KVf[ks * 8 + tig][dt * 8 + grp]);
                uint32_t b1 = __float_as_uint(KVf[ks * 8 + tig + 4][dt * 8 + grp]);
                mma_tf32(acc[dt], a0, a1, a2, a3, b0, b1);
            }
        }
        __syncthreads();      // all V reads done

        // ---- prefetch next K ----
        if (kt + 1 < NT) {
            const float* src = k + ((size_t)((kt + 1) * 64 + ldr) * KVh + kvh) * DHd + ldc;
            uint32_t dst = kv_s + (ldr * 68 + ldc) * 4;
            #pragma unroll
            for (int i = 0; i < 8; ++i) cp_async16(dst + i * 16, src + i * 4);
            cp_commit();
        }
    }

    // epilogue
    float r0inv = 1.f / l0, r1inv = 1.f / l1;
    int row0g = q0 + wr0 + grp;
    int row1g = row0g + 8;
    #pragma unroll
    for (int dt = 0; dt < 8; ++dt) {
        int cg = dt * 8 + tig * 2;
        *(float2*)&o[((size_t)row0g * Hh + h) * DHd + cg] =
            make_float2(acc[dt][0] * r0inv, acc[dt][1] * r0inv);
        *(float2*)&o[((size_t)row1g * Hh + h) * DHd + cg] =
            make_float2(acc[dt][2] * r1inv, acc[dt][3] * r1inv);
    }
}

// ---------------- rmsnorm (float4 vectorized) ----------------
__global__ void rmsnorm_kernel(const float* __restrict__ x, const float* __restrict__ w,
                               float* __restrict__ y)
{
    int n = blockIdx.x;
    const float4* xr = (const float4*)(x + (size_t)n * Dk);
    const float4* wr = (const float4*)w;
    float4*       yr = (float4*)(y + (size_t)n * Dk);
    float s = 0.f;
    float4 v = xr[threadIdx.x];
    s = v.x * v.x + v.y * v.y + v.z * v.z + v.w * v.w;
    __shared__ float red[8];
    int lane = threadIdx.x & 31, wid = threadIdx.x >> 5;
    #pragma unroll
    for (int o = 16; o; o >>= 1) s += __shfl_xor_sync(0xffffffffu, s, o);
    if (lane == 0) red[wid] = s;
    __syncthreads();
    if (wid == 0) {
        float t = (lane < 8) ? red[lane] : 0.f;
        #pragma unroll
        for (int o = 4; o; o >>= 1) t += __shfl_xor_sync(0xffffffffu, t, o);
        if (lane == 0) red[0] = rsqrtf(t / Dk + EPS);
    }
    __syncthreads();
    float rms = red[0];
    float4 wv = wr[threadIdx.x];
    float4 out;
    out.x = v.x * rms * wv.x;
    out.y = v.y * rms * wv.y;
    out.z = v.z * rms * wv.z;
    out.w = v.w * rms * wv.w;
    yr[threadIdx.x] = out;
}

// ---------------- q/k rmsnorm + rope (stores tf32-rounded; q pre-scaled) ----
__global__ void qknorm_rope_kernel(float* __restrict__ q, float* __restrict__ k,
                                   const int* __restrict__ positions,
                                   const float* __restrict__ qw, const float* __restrict__ kw)
{
    int n = blockIdx.x;
    int hh = blockIdx.y;
    float* x; const float* w;
    bool isQ = (hh < Hh);
    if (isQ) { x = q + ((size_t)n * Hh + hh) * DHd; w = qw; }
    else     { x = k + ((size_t)n * KVh + (hh - Hh)) * DHd; w = kw; }
    int lane = threadIdx.x;
    float x1 = x[lane], x2 = x[lane + 32];
    float s = x1 * x1 + x2 * x2;
    #pragma unroll
    for (int o = 16; o; o >>= 1) s += __shfl_xor_sync(0xffffffffu, s, o);
    float rms = rsqrtf(s / 64.f + EPS);
    float v1 = x1 * rms * w[lane];
    float v2 = x2 * rms * w[lane + 32];
    float inv = (float)exp(-(2.0 * (double)lane / 64.0) * log(10000.0));
    float ang = (float)positions[n] * inv;
    float c = cosf(ang), sn = sinf(ang);
    float o1 = v1 * c - v2 * sn;
    float o2 = v2 * c + v1 * sn;
    if (isQ) { o1 *= 0.125f; o2 *= 0.125f; }   // fold attention scale into q
    x[lane]      = __uint_as_float(cvt_tf32(o1));
    x[lane + 32] = __uint_as_float(cvt_tf32(o2));
}

// ---------------- dynamics (elementwise, float4) ----------------
__global__ void dynamics_kernel(const float4* __restrict__ hidden_in,
                                const float4* __restrict__ velocity,
                                const float4* __restrict__ oproj,
                                const float4* __restrict__ mu,
                                const float* __restrict__ co,
                                float4* __restrict__ v_out,
                                float4* __restrict__ hidden2)
{
    int idx = blockIdx.x * blockDim.x + threadIdx.x;
    if (idx >= Nn * Dk / 4) return;
    int n = idx / (Dk / 4), c4 = idx - n * (Dk / 4);
    const float4* cr = (const float4*)(co + (size_t)n * 3 * Dk);
    float4 a_raw  = cr[c4];
    float4 b_raw  = cr[Dk / 4 + c4];
    float4 gt_raw = cr[2 * Dk / 4 + c4];
    float4 ov  = oproj[idx];
    float4 muv = mu[idx];
    float4 vel = velocity[idx];
    float4 hin = hidden_in[idx];
    float4 vn, h2;
    #pragma unroll
    for (int j = 0; j < 4; ++j) {
        float ar = (&a_raw.x)[j], br = (&b_raw.x)[j], gr = (&gt_raw.x)[j];
        float alpha = 1.f / (1.f + expf(-ar));
        float sp = (br > 20.f) ? br : log1pf(expf(br));
        float beta = fminf(sp, 2.f);
        float gate = 1.f / (1.f + expf(-gr));
        float o = (&ov.x)[j];
        float err = o - (&muv.x)[j];
        float vv = alpha * (&vel.x)[j] - beta * err;
        vv = fminf(fmaxf(vv, -10.f), 10.f);
        (&vn.x)[j] = vv;
        (&h2.x)[j] = (&hin.x)[j] + o + DT * gate * vv;
    }
    v_out[idx] = vn;
    hidden2[idx] = h2;
}

// ---------------- router ----------------
__global__ void reset_counts_kernel()
{
    if (threadIdx.x < Ee) g_counts[threadIdx.x] = 0;
}

__global__ void router_kernel(const float* __restrict__ mu, const float* __restrict__ W,
                              const int* __restrict__ token_ids)
{
    int gwarp = (blockIdx.x * blockDim.x + threadIdx.x) >> 5;
    int lane = threadIdx.x & 31;
    if (gwarp >= Nn) return;
    float acc[Ee] = {};
    const float* m = mu + (size_t)gwarp * Dk;
    for (int d = lane; d < Dk; d += 32) {
        float mv = m[d];
        #pragma unroll
        for (int e = 0; e < Ee; ++e) acc[e] += mv * W[d * Ee + e];
    }
    #pragma unroll
    for (int o = 16; o; o >>= 1)
        #pragma unroll
        for (int e = 0; e < Ee; ++e) acc[e] += __shfl_xor_sync(0xffffffffu, acc[e], o);
    if (lane == 0) {
        int base = token_ids[gwarp] % Ee;
        int best = 0; float bv = -1e30f;
        #pragma unroll
        for (int e = 0; e < Ee; ++e) {
            float vv = acc[e] + (e == base ? BASE_SCALE : 0.f);
            if (vv > bv) { bv = vv; best = e; }
        }
        int pos = atomicAdd(&g_counts[best], 1);
        g_list[best * Nn + pos] = gwarp;
    }
}

// ---------------- silu(g)*u elementwise ----------------
__global__ void silumul_kernel(const float4* __restrict__ G, const float4* __restrict__ U,
                               float4* __restrict__ Mid)
{
    int idx = blockIdx.x * blockDim.x + threadIdx.x;
    if (idx >= Nn * Ff / 4) return;
    float4 g = G[idx], u = U[idx], o;
    #pragma unroll
    for (int j = 0; j < 4; ++j) {
        float gv = (&g.x)[j];
        float sg = gv / (1.f + expf(-gv));
        (&o.x)[j] = sg * (&u.x)[j];
    }
    Mid[idx] = o;
}

// ---------------- launch ----------------
static float* sym(const void* s)
{
    void* p = nullptr;
    cudaGetSymbolAddress(&p, s);
    return (float*)p;
}

extern "C" void kernel_launch(void* const* d_in, const int* in_sizes, int n_in,
                              void* d_out, int out_size)
{
    const float* hidden        = (const float*)d_in[0];
    const int*   positions     = (const int*)  d_in[1];
    const float* velocity      = (const float*)d_in[2];
    const int*   token_ids     = (const int*)  d_in[3];
    const float* mu_prev       = (const float*)d_in[4];
    const float* ln1_w         = (const float*)d_in[5];
    const float* ln2_w         = (const float*)d_in[6];
    const float* wq            = (const float*)d_in[7];
    const float* wk            = (const float*)d_in[8];
    const float* wv            = (const float*)d_in[9];
    const float* wo            = (const float*)d_in[10];
    const float* w_mu_q        = (const float*)d_in[11];
    const float* w_mu_k        = (const float*)d_in[12];
    const float* w_mu_v        = (const float*)d_in[13];
    const float* qnorm_w       = (const float*)d_in[14];
    const float* knorm_w       = (const float*)d_in[15];
    const float* dyn_mu        = (const float*)d_in[16];
    const float* dyn_mu_proj_w = (const float*)d_in[17];
    const float* ctrl_in_w     = (const float*)d_in[18];
    const float* ctrl_in_b     = (const float*)d_in[19];
    const float* ctrl_out_w    = (const float*)d_in[20];
    const float* ctrl_out_b    = (const float*)d_in[21];
    const float* mu_router_w   = (const float*)d_in[22];
    const float* w_gate        = (const float*)d_in[23];
    const float* w_up          = (const float*)d_in[24];
    const float* w_down        = (const float*)d_in[25];

    float* out_hidden = (float*)d_out;
    float* out_v      = out_hidden + (size_t)Nn * Dk;
    float* out_mu     = out_v + (size_t)Nn * Dk;

    float* h1   = sym(g_h1);
    float* qb   = sym(g_q);
    float* kb   = sym(g_k);
    float* vb   = sym(g_v);
    float* ob   = sym(g_o);
    float* op   = sym(g_oproj);
    float* ctrl = sym(g_ctrl);
    float* co   = sym(g_co);
    float* h2   = sym(g_hidden2);
    float* x2   = sym(g_x2);
    float* midg = sym(g_midg);
    float* midu = sym(g_midu);
    float* mid  = sym(g_mid);

    // 1) rmsnorm1
    rmsnorm_kernel<<<Nn, 256>>>(hidden, ln1_w, h1);

    // 2) fused QKV = h1@W + mu_prev@W_mu  (tf32 mma; V rounded to tf32 grid)
    qkv_mma_kernel<<<dim3(12, Nn / 128), 256>>>(h1, mu_prev, wq, w_mu_q, wk, w_mu_k,
                                                wv, w_mu_v, qb, kb, vb);

    // 3) q/k norm + rope (in place; stores tf32-rounded, q pre-scaled by 1/8)
    qknorm_rope_kernel<<<dim3(Nn, Hh + KVh), 32>>>(qb, kb, positions, qnorm_w, knorm_w);

    // 4) attention (tf32 mma, v3 structure, no in-loop cvt)
    attn_mma_kernel<<<dim3(Nn / 64, Hh), 128>>>(qb, kb, vb, ob);

    // 5) o-proj (tf32)
    mma_gemm_kernel<false, false, false, 128, 0><<<dim3(Dk / 128, Nn / 128), 256>>>(
        ob, wo, nullptr, nullptr, nullptr, nullptr, op, Dk, Hh * DHd, Hh * DHd, Dk);

    // 6) mu_cur = dyn_mu + oproj @ dyn_mu_proj_w (tf32, direct to output)
    mma_gemm_kernel<false, false, false, 128, 0><<<dim3(Dk / 128, Nn / 128), 256>>>(
        op, dyn_mu_proj_w, nullptr, nullptr, dyn_mu, nullptr, out_mu, Dk, Dk, Dk, Dk);

    // 7) ctrl = silu([o, velocity] @ ctrl_in_w + b)  (tf32 BN=64, dual, silu)
    mma_gemm_kernel<false, true, false, 64, 1><<<dim3(1, Nn / 128), 256>>>(
        op, ctrl_in_w, velocity, ctrl_in_w + (size_t)Dk * CHc, ctrl_in_b, nullptr,
        ctrl, CHc, Dk, Dk, CHc);

    // 8) co = ctrl @ ctrl_out_w + b  (tf32, K=64)
    mma_gemm_kernel<false, false, false, 128, 0><<<dim3(3 * Dk / 128, Nn / 128), 256>>>(
        ctrl, ctrl_out_w, nullptr, nullptr, ctrl_out_b, nullptr, co, 3 * Dk, CHc, CHc, 3 * Dk);

    // 9) dynamics: v_next (output), hidden2
    dynamics_kernel<<<(Nn * Dk / 4 + 255) / 256, 256>>>((const float4*)hidden, (const float4*)velocity,
                                                        (const float4*)op, (const float4*)out_mu, co,
                                                        (float4*)out_v, (float4*)h2);

    // 10) rmsnorm2
    rmsnorm_kernel<<<Nn, 256>>>(h2, ln2_w, x2);

    // 11) router
    reset_counts_kernel<<<1, 32>>>();
    router_kernel<<<(Nn * 32 + 255) / 256, 256>>>(out_mu, mu_router_w, token_ids);

    // 12) MoE gate & up (tf32, gathered)
    mma_gemm_kernel<true, false, false, 128, 0><<<dim3(Ff / 128, Nn / 128, Ee), 256>>>(
        x2, w_gate, nullptr, nullptr, nullptr, nullptr, midg, Ff, Dk, Dk, Ff);
    mma_gemm_kernel<true, false, false, 128, 0><<<dim3(Ff / 128, Nn / 128, Ee), 256>>>(
        x2, w_up, nullptr, nullptr, nullptr, nullptr, midu, Ff, Dk, Dk, Ff);

    // 12b) mid = silu(g) * u
    silumul_kernel<<<(Nn * Ff / 4 + 255) / 256, 256>>>((const float4*)midg, (const float4*)midu,
                                                       (float4*)mid);

    // 13) MoE down + residual -> final hidden (tf32, gathered)
    mma_gemm_kernel<true, false, true, 128, 0><<<dim3(Dk / 128, Nn / 128, Ee), 256>>>(
        mid, w_down, nullptr, nullptr, nullptr, h2, out_hidden, Dk, Ff, Ff, Dk);
}